// round 4
// baseline (speedup 1.0000x reference)
#include <cuda_runtime.h>
#include <cuda_bf16.h>

// HungarianMatcher cost matrix:
//   C[bq, t] = 1*(-softmax(logits[bq])[label_t])
//            + 5*L1(pred_box[bq], tgt_box[t])            (cxcywh space)
//            + 2*(-GIoU(xyxy(pred_box[bq]), xyxy(tgt_box[t])))
//
// Inputs (metadata order):
//   d_in[0] pred_logits  float32 [B,Q,C]
//   d_in[1] pred_boxes   float32 [B,Q,4]
//   d_in[2] tgt_labels   int32   [T]
//   d_in[3] tgt_boxes    float32 [T,4]
// Output: float32 [B,Q,T]

#define BLOCK 256

__global__ __launch_bounds__(BLOCK)
void matcher_kernel(const float* __restrict__ logits,
                    const float* __restrict__ boxes,
                    const int*   __restrict__ labels,
                    const float* __restrict__ tboxes,
                    float*       __restrict__ out,
                    int C, int T)
{
    __shared__ float prob[256];   // C <= 256
    __shared__ float red[BLOCK / 32];

    const int row = blockIdx.x;
    const int tid = threadIdx.x;
    const int wid = tid >> 5;
    const int lid = tid & 31;

    // ---- per-row softmax over C classes ----
    float v = (tid < C) ? logits[(size_t)row * C + tid] : -3.0e38f;

    // block max
    float m = v;
    #pragma unroll
    for (int o = 16; o; o >>= 1) m = fmaxf(m, __shfl_xor_sync(0xffffffffu, m, o));
    if (lid == 0) red[wid] = m;
    __syncthreads();
    float bm = red[0];
    #pragma unroll
    for (int i = 1; i < BLOCK / 32; i++) bm = fmaxf(bm, red[i]);
    __syncthreads();   // everyone done reading red before reuse

    float e = (tid < C) ? __expf(v - bm) : 0.0f;
    float s = e;
    #pragma unroll
    for (int o = 16; o; o >>= 1) s += __shfl_xor_sync(0xffffffffu, s, o);
    if (lid == 0) red[wid] = s;
    __syncthreads();
    float bs = red[0];
    #pragma unroll
    for (int i = 1; i < BLOCK / 32; i++) bs += red[i];

    if (tid < C) prob[tid] = __fdividef(e, bs);
    __syncthreads();

    // ---- per-row pred box precompute ----
    const float4 pb = reinterpret_cast<const float4*>(boxes)[row];  // cx cy w h
    const float px1 = pb.x - 0.5f * pb.z;
    const float py1 = pb.y - 0.5f * pb.w;
    const float px2 = pb.x + 0.5f * pb.z;
    const float py2 = pb.y + 0.5f * pb.w;
    const float parea = (px2 - px1) * (py2 - py1);   // match reference numerics

    float* orow = out + (size_t)row * T;

    // ---- inner loop over targets; coalesced streaming stores ----
    for (int t = tid; t < T; t += BLOCK) {
        const float4 tb = reinterpret_cast<const float4*>(tboxes)[t];
        const int   lab = labels[t];
        const float cls = prob[lab];

        // L1 in cxcywh space
        const float l1 = fabsf(pb.x - tb.x) + fabsf(pb.y - tb.y)
                       + fabsf(pb.z - tb.z) + fabsf(pb.w - tb.w);

        // GIoU in xyxy
        const float tx1 = tb.x - 0.5f * tb.z;
        const float ty1 = tb.y - 0.5f * tb.w;
        const float tx2 = tb.x + 0.5f * tb.z;
        const float ty2 = tb.y + 0.5f * tb.w;
        const float tarea = (tx2 - tx1) * (ty2 - ty1);

        const float iw = fmaxf(fminf(px2, tx2) - fmaxf(px1, tx1), 0.0f);
        const float ih = fmaxf(fminf(py2, ty2) - fmaxf(py1, ty1), 0.0f);
        const float inter = iw * ih;
        const float uni = parea + tarea - inter;
        const float iou = __fdividef(inter, uni);

        const float ew = fmaxf(fmaxf(px2, tx2) - fminf(px1, tx1), 0.0f);
        const float eh = fmaxf(fmaxf(py2, ty2) - fminf(py1, ty1), 0.0f);
        const float earea = ew * eh;
        const float giou = iou - __fdividef(earea - uni, earea);

        const float cost = -cls + 5.0f * l1 - 2.0f * giou;
        __stcs(orow + t, cost);
    }
}

extern "C" void kernel_launch(void* const* d_in, const int* in_sizes, int n_in,
                              void* d_out, int out_size)
{
    const float* logits = (const float*)d_in[0];
    const float* boxes  = (const float*)d_in[1];
    const int*   labels = (const int*)  d_in[2];
    const float* tboxes = (const float*)d_in[3];
    float* out = (float*)d_out;

    const int BQ = in_sizes[1] / 4;          // pred_boxes is [BQ, 4]
    const int C  = in_sizes[0] / BQ;         // logits [BQ, C]
    const int T  = in_sizes[2];              // labels [T]

    matcher_kernel<<<BQ, BLOCK>>>(logits, boxes, labels, tboxes, out, C, T);
}

// round 7
// speedup vs baseline: 1.2790x; 1.2790x over previous
#include <cuda_runtime.h>
#include <cuda_bf16.h>

// HungarianMatcher cost matrix:
//   C[bq, t] = -softmax(logits[bq])[label_t]
//            + 5*L1(pred_box[bq], tgt_box[t])            (cxcywh space)
//            - 2*GIoU(xyxy(pred_box[bq]), xyxy(tgt_box[t]))
//
// Inputs: d_in[0] pred_logits f32 [B,Q,C], d_in[1] pred_boxes f32 [B,Q,4],
//         d_in[2] tgt_labels i32 [T],      d_in[3] tgt_boxes  f32 [T,4]
// Output: f32 [B,Q,T]
//
// Structure: thread owns one target t (all per-t state in registers);
// CTA covers RB=16 rows whose softmax probs + box params live in smem.

#define BLOCK 256
#define RB    16
#define CPAD  96   // padded class stride (C <= 96)

__global__ __launch_bounds__(BLOCK)
void matcher_rt_kernel(const float* __restrict__ logits,
                       const float* __restrict__ boxes,
                       const int*   __restrict__ labels,
                       const float* __restrict__ tboxes,
                       float*       __restrict__ out,
                       int BQ, int C, int T)
{
    __shared__ float sprob[RB][CPAD];  // softmax probs per row
    __shared__ float srp[RB][8];       // px1,py1,px2,py2, pcx,pcy,pw,ph
    __shared__ float sparea[RB];

    const int tid = threadIdx.x;
    const int wid = tid >> 5;
    const int lid = tid & 31;
    const int row0 = blockIdx.y * RB;

    // ---- setup: 8 warps, each computes softmax + box params for 2 rows ----
    for (int rr = wid; rr < RB; rr += (BLOCK / 32)) {
        const int row = row0 + rr;
        if (row < BQ) {
            const float* lrow = logits + (size_t)row * C;
            float v0 = (lid      < C) ? lrow[lid]      : -3.0e38f;
            float v1 = (lid + 32 < C) ? lrow[lid + 32] : -3.0e38f;
            float v2 = (lid + 64 < C) ? lrow[lid + 64] : -3.0e38f;
            float m = fmaxf(fmaxf(v0, v1), v2);
            #pragma unroll
            for (int o = 16; o; o >>= 1) m = fmaxf(m, __shfl_xor_sync(0xffffffffu, m, o));
            float e0 = __expf(v0 - m), e1 = __expf(v1 - m), e2 = __expf(v2 - m);
            float s = e0 + e1 + e2;
            #pragma unroll
            for (int o = 16; o; o >>= 1) s += __shfl_xor_sync(0xffffffffu, s, o);
            const float rinv = __fdividef(1.0f, s);
            if (lid      < C) sprob[rr][lid]      = e0 * rinv;
            if (lid + 32 < C) sprob[rr][lid + 32] = e1 * rinv;
            if (lid + 64 < C) sprob[rr][lid + 64] = e2 * rinv;
            if (lid == 0) {
                const float4 pb = reinterpret_cast<const float4*>(boxes)[row];
                const float px1 = pb.x - 0.5f * pb.z;
                const float py1 = pb.y - 0.5f * pb.w;
                const float px2 = pb.x + 0.5f * pb.z;
                const float py2 = pb.y + 0.5f * pb.w;
                srp[rr][0] = px1;  srp[rr][1] = py1;
                srp[rr][2] = px2;  srp[rr][3] = py2;
                srp[rr][4] = pb.x; srp[rr][5] = pb.y;
                srp[rr][6] = pb.z; srp[rr][7] = pb.w;
                sparea[rr] = (px2 - px1) * (py2 - py1);
            }
        }
    }
    __syncthreads();

    // ---- per-thread target state (hoisted for all RB rows) ----
    const int t = blockIdx.x * BLOCK + tid;
    if (t >= T) return;

    const float4 tb = reinterpret_cast<const float4*>(tboxes)[t];
    const int   lab = labels[t];
    const float tx1 = tb.x - 0.5f * tb.z;
    const float ty1 = tb.y - 0.5f * tb.w;
    const float tx2 = tb.x + 0.5f * tb.z;
    const float ty2 = tb.y + 0.5f * tb.w;
    const float tarea = (tx2 - tx1) * (ty2 - ty1);

    float* op = out + (size_t)row0 * T + t;
    const int rmax = min(RB, BQ - row0);

    if (rmax == RB) {
        #pragma unroll
        for (int r = 0; r < RB; r++) {
            const float4 A  = *reinterpret_cast<const float4*>(&srp[r][0]); // px1 py1 px2 py2
            const float4 Bv = *reinterpret_cast<const float4*>(&srp[r][4]); // pcx pcy pw  ph
            const float parea = sparea[r];
            const float cls   = sprob[r][lab];

            const float l1 = fabsf(Bv.x - tb.x) + fabsf(Bv.y - tb.y)
                           + fabsf(Bv.z - tb.z) + fabsf(Bv.w - tb.w);

            const float iwr = fminf(A.z, tx2) - fmaxf(A.x, tx1);
            const float ihr = fminf(A.w, ty2) - fmaxf(A.y, ty1);
            const float inter = fmaxf(iwr, 0.0f) * fmaxf(ihr, 0.0f);
            const float uni   = parea + tarea - inter;
            // enclosing box via min+max identity (no extra FMNMX):
            const float ew = (Bv.z + tb.z) - iwr;
            const float eh = (Bv.w + tb.w) - ihr;
            const float earea = ew * eh;
            // iou - (earea-uni)/earea  ==  (earea*(inter-uni) + uni^2) / (uni*earea)
            const float num   = fmaf(uni, uni, earea * (inter - uni));
            const float gterm = __fdividef(num, uni * earea);

            float cost = fmaf(5.0f, l1, -cls);
            cost = fmaf(-2.0f, gterm, cost);
            __stcs(op, cost);
            op += T;
        }
    } else {
        for (int r = 0; r < rmax; r++) {
            const float4 A  = *reinterpret_cast<const float4*>(&srp[r][0]);
            const float4 Bv = *reinterpret_cast<const float4*>(&srp[r][4]);
            const float parea = sparea[r];
            const float cls   = sprob[r][lab];

            const float l1 = fabsf(Bv.x - tb.x) + fabsf(Bv.y - tb.y)
                           + fabsf(Bv.z - tb.z) + fabsf(Bv.w - tb.w);

            const float iwr = fminf(A.z, tx2) - fmaxf(A.x, tx1);
            const float ihr = fminf(A.w, ty2) - fmaxf(A.y, ty1);
            const float inter = fmaxf(iwr, 0.0f) * fmaxf(ihr, 0.0f);
            const float uni   = parea + tarea - inter;
            const float ew = (Bv.z + tb.z) - iwr;
            const float eh = (Bv.w + tb.w) - ihr;
            const float earea = ew * eh;
            const float num   = fmaf(uni, uni, earea * (inter - uni));
            const float gterm = __fdividef(num, uni * earea);

            float cost = fmaf(5.0f, l1, -cls);
            cost = fmaf(-2.0f, gterm, cost);
            __stcs(op, cost);
            op += T;
        }
    }
}

// ---- generic fallback (C > 96): original row-per-CTA kernel ----
__global__ __launch_bounds__(BLOCK)
void matcher_fallback_kernel(const float* __restrict__ logits,
                             const float* __restrict__ boxes,
                             const int*   __restrict__ labels,
                             const float* __restrict__ tboxes,
                             float*       __restrict__ out,
                             int C, int T)
{
    __shared__ float prob[1024];
    __shared__ float red[BLOCK / 32];

    const int row = blockIdx.x;
    const int tid = threadIdx.x;
    const int wid = tid >> 5;
    const int lid = tid & 31;

    float m = -3.0e38f;
    for (int c = tid; c < C; c += BLOCK) m = fmaxf(m, logits[(size_t)row * C + c]);
    #pragma unroll
    for (int o = 16; o; o >>= 1) m = fmaxf(m, __shfl_xor_sync(0xffffffffu, m, o));
    if (lid == 0) red[wid] = m;
    __syncthreads();
    float bm = red[0];
    #pragma unroll
    for (int i = 1; i < BLOCK / 32; i++) bm = fmaxf(bm, red[i]);
    __syncthreads();

    float s = 0.0f;
    for (int c = tid; c < C; c += BLOCK) {
        float e = __expf(logits[(size_t)row * C + c] - bm);
        prob[c] = e;
        s += e;
    }
    #pragma unroll
    for (int o = 16; o; o >>= 1) s += __shfl_xor_sync(0xffffffffu, s, o);
    if (lid == 0) red[wid] = s;
    __syncthreads();
    float bs = red[0];
    #pragma unroll
    for (int i = 1; i < BLOCK / 32; i++) bs += red[i];
    float rinv = __fdividef(1.0f, bs);
    __syncthreads();
    for (int c = tid; c < C; c += BLOCK) prob[c] *= rinv;
    __syncthreads();

    const float4 pb = reinterpret_cast<const float4*>(boxes)[row];
    const float px1 = pb.x - 0.5f * pb.z, py1 = pb.y - 0.5f * pb.w;
    const float px2 = pb.x + 0.5f * pb.z, py2 = pb.y + 0.5f * pb.w;
    const float parea = (px2 - px1) * (py2 - py1);
    float* orow = out + (size_t)row * T;

    for (int t = tid; t < T; t += BLOCK) {
        const float4 tb = reinterpret_cast<const float4*>(tboxes)[t];
        const float cls = prob[labels[t]];
        const float l1 = fabsf(pb.x - tb.x) + fabsf(pb.y - tb.y)
                       + fabsf(pb.z - tb.z) + fabsf(pb.w - tb.w);
        const float tx1 = tb.x - 0.5f * tb.z, ty1 = tb.y - 0.5f * tb.w;
        const float tx2 = tb.x + 0.5f * tb.z, ty2 = tb.y + 0.5f * tb.w;
        const float tarea = (tx2 - tx1) * (ty2 - ty1);
        const float iwr = fminf(px2, tx2) - fmaxf(px1, tx1);
        const float ihr = fminf(py2, ty2) - fmaxf(py1, ty1);
        const float inter = fmaxf(iwr, 0.0f) * fmaxf(ihr, 0.0f);
        const float uni = parea + tarea - inter;
        const float ew = (pb.z + tb.z) - iwr;
        const float eh = (pb.w + tb.w) - ihr;
        const float earea = ew * eh;
        const float num   = fmaf(uni, uni, earea * (inter - uni));
        const float gterm = __fdividef(num, uni * earea);
        float cost = fmaf(5.0f, l1, -cls);
        cost = fmaf(-2.0f, gterm, cost);
        __stcs(orow + t, cost);
    }
}

extern "C" void kernel_launch(void* const* d_in, const int* in_sizes, int n_in,
                              void* d_out, int out_size)
{
    const float* logits = (const float*)d_in[0];
    const float* boxes  = (const float*)d_in[1];
    const int*   labels = (const int*)  d_in[2];
    const float* tboxes = (const float*)d_in[3];
    float* out = (float*)d_out;

    const int BQ = in_sizes[1] / 4;          // pred_boxes is [BQ, 4]
    const int C  = in_sizes[0] / BQ;         // logits [BQ, C]
    const int T  = in_sizes[2];              // labels [T]

    if (C <= CPAD) {
        dim3 grid((T + BLOCK - 1) / BLOCK, (BQ + RB - 1) / RB);
        matcher_rt_kernel<<<grid, BLOCK>>>(logits, boxes, labels, tboxes, out, BQ, C, T);
    } else {
        matcher_fallback_kernel<<<BQ, BLOCK>>>(logits, boxes, labels, tboxes, out, C, T);
    }
}

// round 8
// speedup vs baseline: 1.5251x; 1.1924x over previous
#include <cuda_runtime.h>
#include <cuda_bf16.h>

// HungarianMatcher cost matrix:
//   C[bq, t] = -softmax(logits[bq])[label_t]
//            + 5*L1(pred_box[bq], tgt_box[t])            (cxcywh space)
//            - 2*GIoU(xyxy(pred_box[bq]), xyxy(tgt_box[t]))
//
// Inputs: d_in[0] pred_logits f32 [B,Q,C], d_in[1] pred_boxes f32 [B,Q,4],
//         d_in[2] tgt_labels i32 [T],      d_in[3] tgt_boxes  f32 [T,4]
// Output: f32 [B,Q,T]
//
// Structure: thread owns TWO targets (t, t+BLOCK), all per-t state in
// registers; CTA covers RB=16 rows whose softmax probs + box params live in
// smem. T=2048 template specialization gives immediate-offset stores.

#define BLOCK 256
#define RB    16
#define TB    2      // targets per thread
#define CPAD  96     // padded class stride (C <= 96)

struct TgtState {
    float4 tb;                  // cx cy w h
    float tx1, ty1, tx2, ty2;   // xyxy
    float tarea;
    int   lab;
};

__device__ __forceinline__ void load_tgt(TgtState& s, const float* __restrict__ tboxes,
                                         const int* __restrict__ labels, int t)
{
    s.tb  = reinterpret_cast<const float4*>(tboxes)[t];
    s.lab = labels[t];
    s.tx1 = s.tb.x - 0.5f * s.tb.z;
    s.ty1 = s.tb.y - 0.5f * s.tb.w;
    s.tx2 = s.tb.x + 0.5f * s.tb.z;
    s.ty2 = s.tb.y + 0.5f * s.tb.w;
    s.tarea = (s.tx2 - s.tx1) * (s.ty2 - s.ty1);
}

// cost for one (row, target) pair; A = px1 py1 px2 py2, Bv = pcx pcy pw ph
__device__ __forceinline__ float pair_cost(const float4 A, const float4 Bv,
                                           const float parea, const TgtState& s,
                                           const float cls)
{
    const float l1 = fabsf(Bv.x - s.tb.x) + fabsf(Bv.y - s.tb.y)
                   + fabsf(Bv.z - s.tb.z) + fabsf(Bv.w - s.tb.w);

    const float iwr = fminf(A.z, s.tx2) - fmaxf(A.x, s.tx1);
    const float ihr = fminf(A.w, s.ty2) - fmaxf(A.y, s.ty1);
    const float inter = fmaxf(iwr, 0.0f) * fmaxf(ihr, 0.0f);
    const float uni   = parea + s.tarea - inter;
    // enclosing box via min+max identity:
    const float ew = (Bv.z + s.tb.z) - iwr;
    const float eh = (Bv.w + s.tb.w) - ihr;
    const float earea = ew * eh;
    // iou - (earea-uni)/earea == (earea*(inter-uni) + uni^2) / (uni*earea)
    const float num   = fmaf(uni, uni, earea * (inter - uni));
    const float gterm = __fdividef(num, uni * earea);

    float cost = fmaf(5.0f, l1, -cls);
    return fmaf(-2.0f, gterm, cost);
}

template<int TCONST>
__global__ __launch_bounds__(BLOCK)
void matcher_rt2_kernel(const float* __restrict__ logits,
                        const float* __restrict__ boxes,
                        const int*   __restrict__ labels,
                        const float* __restrict__ tboxes,
                        float*       __restrict__ out,
                        int BQ, int C, int T_rt)
{
    const int T = TCONST ? TCONST : T_rt;

    __shared__ float sprob[RB][CPAD];  // softmax probs per row
    __shared__ float srp[RB][12];      // px1,py1,px2,py2, pcx,pcy,pw,ph, parea, pad

    const int tid = threadIdx.x;
    const int wid = tid >> 5;
    const int lid = tid & 31;
    const int row0 = blockIdx.y * RB;

    // ---- setup: 8 warps, each does softmax + box params for 2 rows ----
    for (int rr = wid; rr < RB; rr += (BLOCK / 32)) {
        const int row = row0 + rr;
        if (row < BQ) {
            const float* lrow = logits + (size_t)row * C;
            float v0 = (lid      < C) ? lrow[lid]      : -3.0e38f;
            float v1 = (lid + 32 < C) ? lrow[lid + 32] : -3.0e38f;
            float v2 = (lid + 64 < C) ? lrow[lid + 64] : -3.0e38f;
            float m = fmaxf(fmaxf(v0, v1), v2);
            #pragma unroll
            for (int o = 16; o; o >>= 1) m = fmaxf(m, __shfl_xor_sync(0xffffffffu, m, o));
            float e0 = __expf(v0 - m), e1 = __expf(v1 - m), e2 = __expf(v2 - m);
            float s = e0 + e1 + e2;
            #pragma unroll
            for (int o = 16; o; o >>= 1) s += __shfl_xor_sync(0xffffffffu, s, o);
            const float rinv = __fdividef(1.0f, s);
            if (lid      < C) sprob[rr][lid]      = e0 * rinv;
            if (lid + 32 < C) sprob[rr][lid + 32] = e1 * rinv;
            if (lid + 64 < C) sprob[rr][lid + 64] = e2 * rinv;
            if (lid == 0) {
                const float4 pb = reinterpret_cast<const float4*>(boxes)[row];
                const float px1 = pb.x - 0.5f * pb.z;
                const float py1 = pb.y - 0.5f * pb.w;
                const float px2 = pb.x + 0.5f * pb.z;
                const float py2 = pb.y + 0.5f * pb.w;
                srp[rr][0] = px1;  srp[rr][1] = py1;
                srp[rr][2] = px2;  srp[rr][3] = py2;
                srp[rr][4] = pb.x; srp[rr][5] = pb.y;
                srp[rr][6] = pb.z; srp[rr][7] = pb.w;
                srp[rr][8] = (px2 - px1) * (py2 - py1);
            }
        }
    }
    __syncthreads();

    // ---- per-thread target state for 2 targets ----
    const int t0 = blockIdx.x * (BLOCK * TB) + tid;
    const int t1 = t0 + BLOCK;
    if (t0 >= T) return;
    const bool has1 = TCONST ? true : (t1 < T);

    TgtState s0, s1;
    load_tgt(s0, tboxes, labels, t0);
    load_tgt(s1, tboxes, labels, has1 ? t1 : t0);

    float* base = out + (size_t)row0 * T + t0;
    const int rmax = min(RB, BQ - row0);

    if (rmax == RB && has1) {
        #pragma unroll
        for (int r = 0; r < RB; r++) {
            const float4 A     = *reinterpret_cast<const float4*>(&srp[r][0]);
            const float4 Bv    = *reinterpret_cast<const float4*>(&srp[r][4]);
            const float  parea = srp[r][8];
            const float c0 = pair_cost(A, Bv, parea, s0, sprob[r][s0.lab]);
            const float c1 = pair_cost(A, Bv, parea, s1, sprob[r][s1.lab]);
            __stcs(base + (size_t)r * T,         c0);
            __stcs(base + (size_t)r * T + BLOCK, c1);
        }
    } else {
        for (int r = 0; r < rmax; r++) {
            const float4 A     = *reinterpret_cast<const float4*>(&srp[r][0]);
            const float4 Bv    = *reinterpret_cast<const float4*>(&srp[r][4]);
            const float  parea = srp[r][8];
            const float c0 = pair_cost(A, Bv, parea, s0, sprob[r][s0.lab]);
            __stcs(base + (size_t)r * T, c0);
            if (has1) {
                const float c1 = pair_cost(A, Bv, parea, s1, sprob[r][s1.lab]);
                __stcs(base + (size_t)r * T + BLOCK, c1);
            }
        }
    }
}

// ---- generic fallback (C > 96): row-per-CTA kernel ----
__global__ __launch_bounds__(BLOCK)
void matcher_fallback_kernel(const float* __restrict__ logits,
                             const float* __restrict__ boxes,
                             const int*   __restrict__ labels,
                             const float* __restrict__ tboxes,
                             float*       __restrict__ out,
                             int C, int T)
{
    __shared__ float prob[1024];
    __shared__ float red[BLOCK / 32];

    const int row = blockIdx.x;
    const int tid = threadIdx.x;
    const int wid = tid >> 5;
    const int lid = tid & 31;

    float m = -3.0e38f;
    for (int c = tid; c < C; c += BLOCK) m = fmaxf(m, logits[(size_t)row * C + c]);
    #pragma unroll
    for (int o = 16; o; o >>= 1) m = fmaxf(m, __shfl_xor_sync(0xffffffffu, m, o));
    if (lid == 0) red[wid] = m;
    __syncthreads();
    float bm = red[0];
    #pragma unroll
    for (int i = 1; i < BLOCK / 32; i++) bm = fmaxf(bm, red[i]);
    __syncthreads();

    float s = 0.0f;
    for (int c = tid; c < C; c += BLOCK) {
        float e = __expf(logits[(size_t)row * C + c] - bm);
        prob[c] = e;
        s += e;
    }
    #pragma unroll
    for (int o = 16; o; o >>= 1) s += __shfl_xor_sync(0xffffffffu, s, o);
    if (lid == 0) red[wid] = s;
    __syncthreads();
    float bs = red[0];
    #pragma unroll
    for (int i = 1; i < BLOCK / 32; i++) bs += red[i];
    float rinv = __fdividef(1.0f, bs);
    __syncthreads();
    for (int c = tid; c < C; c += BLOCK) prob[c] *= rinv;
    __syncthreads();

    const float4 pb = reinterpret_cast<const float4*>(boxes)[row];
    const float px1 = pb.x - 0.5f * pb.z, py1 = pb.y - 0.5f * pb.w;
    const float px2 = pb.x + 0.5f * pb.z, py2 = pb.y + 0.5f * pb.w;
    const float parea = (px2 - px1) * (py2 - py1);
    float* orow = out + (size_t)row * T;

    for (int t = tid; t < T; t += BLOCK) {
        const float4 tb = reinterpret_cast<const float4*>(tboxes)[t];
        const float cls = prob[labels[t]];
        const float l1 = fabsf(pb.x - tb.x) + fabsf(pb.y - tb.y)
                       + fabsf(pb.z - tb.z) + fabsf(pb.w - tb.w);
        const float tx1 = tb.x - 0.5f * tb.z, ty1 = tb.y - 0.5f * tb.w;
        const float tx2 = tb.x + 0.5f * tb.z, ty2 = tb.y + 0.5f * tb.w;
        const float tarea = (tx2 - tx1) * (ty2 - ty1);
        const float iwr = fminf(px2, tx2) - fmaxf(px1, tx1);
        const float ihr = fminf(py2, ty2) - fmaxf(py1, ty1);
        const float inter = fmaxf(iwr, 0.0f) * fmaxf(ihr, 0.0f);
        const float uni = parea + tarea - inter;
        const float ew = (pb.z + tb.z) - iwr;
        const float eh = (pb.w + tb.w) - ihr;
        const float earea = ew * eh;
        const float num   = fmaf(uni, uni, earea * (inter - uni));
        const float gterm = __fdividef(num, uni * earea);
        float cost = fmaf(5.0f, l1, -cls);
        cost = fmaf(-2.0f, gterm, cost);
        __stcs(orow + t, cost);
    }
}

extern "C" void kernel_launch(void* const* d_in, const int* in_sizes, int n_in,
                              void* d_out, int out_size)
{
    const float* logits = (const float*)d_in[0];
    const float* boxes  = (const float*)d_in[1];
    const int*   labels = (const int*)  d_in[2];
    const float* tboxes = (const float*)d_in[3];
    float* out = (float*)d_out;

    const int BQ = in_sizes[1] / 4;          // pred_boxes is [BQ, 4]
    const int C  = in_sizes[0] / BQ;         // logits [BQ, C]
    const int T  = in_sizes[2];              // labels [T]

    if (C <= CPAD) {
        dim3 grid((T + BLOCK * TB - 1) / (BLOCK * TB), (BQ + RB - 1) / RB);
        if (T == 2048)
            matcher_rt2_kernel<2048><<<grid, BLOCK>>>(logits, boxes, labels, tboxes, out, BQ, C, T);
        else
            matcher_rt2_kernel<0><<<grid, BLOCK>>>(logits, boxes, labels, tboxes, out, BQ, C, T);
    } else {
        matcher_fallback_kernel<<<BQ, BLOCK>>>(logits, boxes, labels, tboxes, out, C, T);
    }
}

// round 9
// speedup vs baseline: 1.7540x; 1.1501x over previous
#include <cuda_runtime.h>
#include <cuda_bf16.h>

// HungarianMatcher cost matrix:
//   C[bq, t] = -softmax(logits[bq])[label_t]
//            + 5*L1(pred_box[bq], tgt_box[t])            (cxcywh space)
//            - 2*GIoU(xyxy(pred_box[bq]), xyxy(tgt_box[t]))
//
// Inputs: d_in[0] pred_logits f32 [B,Q,C], d_in[1] pred_boxes f32 [B,Q,4],
//         d_in[2] tgt_labels i32 [T],      d_in[3] tgt_boxes  f32 [T,4]
// Output: f32 [B,Q,T]
//
// Structure: CTA owns RB=16 rows (softmax probs + box params in smem,
// computed ONCE); each thread owns 4 ADJACENT targets (state in registers),
// looping over T in chunks of BLOCK*TB. Costs for the 4 targets are written
// with a single STG.128. T=2048 specialization -> immediate store offsets.

#define BLOCK 256
#define RB    16
#define TB    4      // adjacent targets per thread
#define CPAD  96     // padded class stride (C <= 96)

struct TgtState {
    float4 tb;                  // cx cy w h
    float tx1, ty1, tx2, ty2;   // xyxy
    float tarea;
    int   lab;
};

__device__ __forceinline__ void make_tgt(TgtState& s, const float4 tb, const int lab)
{
    s.tb  = tb;
    s.lab = lab;
    s.tx1 = tb.x - 0.5f * tb.z;
    s.ty1 = tb.y - 0.5f * tb.w;
    s.tx2 = tb.x + 0.5f * tb.z;
    s.ty2 = tb.y + 0.5f * tb.w;
    s.tarea = (s.tx2 - s.tx1) * (s.ty2 - s.ty1);
}

// cost for one (row, target) pair; A = px1 py1 px2 py2, Bv = pcx pcy pw ph
__device__ __forceinline__ float pair_cost(const float4 A, const float4 Bv,
                                           const float parea, const TgtState& s,
                                           const float cls)
{
    const float l1 = fabsf(Bv.x - s.tb.x) + fabsf(Bv.y - s.tb.y)
                   + fabsf(Bv.z - s.tb.z) + fabsf(Bv.w - s.tb.w);

    const float iwr = fminf(A.z, s.tx2) - fmaxf(A.x, s.tx1);
    const float ihr = fminf(A.w, s.ty2) - fmaxf(A.y, s.ty1);
    const float inter = fmaxf(iwr, 0.0f) * fmaxf(ihr, 0.0f);
    const float uni   = parea + s.tarea - inter;
    // enclosing box via max(a,b) = a+b-min(a,b) identity:
    const float ew = (Bv.z + s.tb.z) - iwr;
    const float eh = (Bv.w + s.tb.w) - ihr;
    const float earea = ew * eh;
    // iou - (earea-uni)/earea == (earea*(inter-uni) + uni^2) / (uni*earea)
    const float num   = fmaf(uni, uni, earea * (inter - uni));
    const float gterm = __fdividef(num, uni * earea);

    float cost = fmaf(5.0f, l1, -cls);
    return fmaf(-2.0f, gterm, cost);
}

template<int TCONST>
__global__ __launch_bounds__(BLOCK)
void matcher_rt4_kernel(const float* __restrict__ logits,
                        const float* __restrict__ boxes,
                        const int*   __restrict__ labels,
                        const float* __restrict__ tboxes,
                        float*       __restrict__ out,
                        int BQ, int C, int T_rt)
{
    const int T = TCONST ? TCONST : T_rt;

    __shared__ float sprob[RB][CPAD];  // softmax probs per row
    __shared__ float srp[RB][12];      // px1,py1,px2,py2, pcx,pcy,pw,ph, parea, pad

    const int tid = threadIdx.x;
    const int wid = tid >> 5;
    const int lid = tid & 31;
    const int row0 = blockIdx.y * RB;

    // ---- setup: 8 warps, each does softmax + box params for 2 rows ----
    for (int rr = wid; rr < RB; rr += (BLOCK / 32)) {
        const int row = row0 + rr;
        if (row < BQ) {
            const float* lrow = logits + (size_t)row * C;
            float v0 = (lid      < C) ? lrow[lid]      : -3.0e38f;
            float v1 = (lid + 32 < C) ? lrow[lid + 32] : -3.0e38f;
            float v2 = (lid + 64 < C) ? lrow[lid + 64] : -3.0e38f;
            float m = fmaxf(fmaxf(v0, v1), v2);
            #pragma unroll
            for (int o = 16; o; o >>= 1) m = fmaxf(m, __shfl_xor_sync(0xffffffffu, m, o));
            float e0 = __expf(v0 - m), e1 = __expf(v1 - m), e2 = __expf(v2 - m);
            float s = e0 + e1 + e2;
            #pragma unroll
            for (int o = 16; o; o >>= 1) s += __shfl_xor_sync(0xffffffffu, s, o);
            const float rinv = __fdividef(1.0f, s);
            if (lid      < C) sprob[rr][lid]      = e0 * rinv;
            if (lid + 32 < C) sprob[rr][lid + 32] = e1 * rinv;
            if (lid + 64 < C) sprob[rr][lid + 64] = e2 * rinv;
            if (lid == 0) {
                const float4 pb = reinterpret_cast<const float4*>(boxes)[row];
                const float px1 = pb.x - 0.5f * pb.z;
                const float py1 = pb.y - 0.5f * pb.w;
                const float px2 = pb.x + 0.5f * pb.z;
                const float py2 = pb.y + 0.5f * pb.w;
                srp[rr][0] = px1;  srp[rr][1] = py1;
                srp[rr][2] = px2;  srp[rr][3] = py2;
                srp[rr][4] = pb.x; srp[rr][5] = pb.y;
                srp[rr][6] = pb.z; srp[rr][7] = pb.w;
                srp[rr][8] = (px2 - px1) * (py2 - py1);
            }
        }
    }
    __syncthreads();

    const int rmax = min(RB, BQ - row0);
    const int nchunks = T / (BLOCK * TB);   // launcher guarantees divisibility

    for (int c = 0; c < nchunks; c++) {
        const int t0 = c * (BLOCK * TB) + tid * TB;

        // 4 adjacent targets: labels as one int4, boxes as 4x float4
        const int4 lab4 = *reinterpret_cast<const int4*>(labels + t0);
        const float4* tbp = reinterpret_cast<const float4*>(tboxes) + t0;
        TgtState s0, s1, s2, s3;
        make_tgt(s0, tbp[0], lab4.x);
        make_tgt(s1, tbp[1], lab4.y);
        make_tgt(s2, tbp[2], lab4.z);
        make_tgt(s3, tbp[3], lab4.w);

        float4* obase = reinterpret_cast<float4*>(out + (size_t)row0 * T + t0);
        const int ostride = T >> 2;   // compile-time for TCONST -> immediate offsets

        if (rmax == RB) {
            #pragma unroll
            for (int r = 0; r < RB; r++) {
                const float4 A     = *reinterpret_cast<const float4*>(&srp[r][0]);
                const float4 Bv    = *reinterpret_cast<const float4*>(&srp[r][4]);
                const float  parea = srp[r][8];
                float4 cst;
                cst.x = pair_cost(A, Bv, parea, s0, sprob[r][s0.lab]);
                cst.y = pair_cost(A, Bv, parea, s1, sprob[r][s1.lab]);
                cst.z = pair_cost(A, Bv, parea, s2, sprob[r][s2.lab]);
                cst.w = pair_cost(A, Bv, parea, s3, sprob[r][s3.lab]);
                __stcs(obase + r * ostride, cst);
            }
        } else {
            for (int r = 0; r < rmax; r++) {
                const float4 A     = *reinterpret_cast<const float4*>(&srp[r][0]);
                const float4 Bv    = *reinterpret_cast<const float4*>(&srp[r][4]);
                const float  parea = srp[r][8];
                float4 cst;
                cst.x = pair_cost(A, Bv, parea, s0, sprob[r][s0.lab]);
                cst.y = pair_cost(A, Bv, parea, s1, sprob[r][s1.lab]);
                cst.z = pair_cost(A, Bv, parea, s2, sprob[r][s2.lab]);
                cst.w = pair_cost(A, Bv, parea, s3, sprob[r][s3.lab]);
                __stcs(obase + r * ostride, cst);
            }
        }
    }
}

// ---- generic fallback (C > 96 or T not divisible): row-per-CTA kernel ----
__global__ __launch_bounds__(BLOCK)
void matcher_fallback_kernel(const float* __restrict__ logits,
                             const float* __restrict__ boxes,
                             const int*   __restrict__ labels,
                             const float* __restrict__ tboxes,
                             float*       __restrict__ out,
                             int C, int T)
{
    __shared__ float prob[1024];
    __shared__ float red[BLOCK / 32];

    const int row = blockIdx.x;
    const int tid = threadIdx.x;
    const int wid = tid >> 5;
    const int lid = tid & 31;

    float m = -3.0e38f;
    for (int c = tid; c < C; c += BLOCK) m = fmaxf(m, logits[(size_t)row * C + c]);
    #pragma unroll
    for (int o = 16; o; o >>= 1) m = fmaxf(m, __shfl_xor_sync(0xffffffffu, m, o));
    if (lid == 0) red[wid] = m;
    __syncthreads();
    float bm = red[0];
    #pragma unroll
    for (int i = 1; i < BLOCK / 32; i++) bm = fmaxf(bm, red[i]);
    __syncthreads();

    float s = 0.0f;
    for (int c = tid; c < C; c += BLOCK) {
        float e = __expf(logits[(size_t)row * C + c] - bm);
        prob[c] = e;
        s += e;
    }
    #pragma unroll
    for (int o = 16; o; o >>= 1) s += __shfl_xor_sync(0xffffffffu, s, o);
    if (lid == 0) red[wid] = s;
    __syncthreads();
    float bs = red[0];
    #pragma unroll
    for (int i = 1; i < BLOCK / 32; i++) bs += red[i];
    float rinv = __fdividef(1.0f, bs);
    __syncthreads();
    for (int c = tid; c < C; c += BLOCK) prob[c] *= rinv;
    __syncthreads();

    const float4 pb = reinterpret_cast<const float4*>(boxes)[row];
    const float px1 = pb.x - 0.5f * pb.z, py1 = pb.y - 0.5f * pb.w;
    const float px2 = pb.x + 0.5f * pb.z, py2 = pb.y + 0.5f * pb.w;
    const float parea = (px2 - px1) * (py2 - py1);
    float* orow = out + (size_t)row * T;

    for (int t = tid; t < T; t += BLOCK) {
        const float4 tb = reinterpret_cast<const float4*>(tboxes)[t];
        const float cls = prob[labels[t]];
        const float l1 = fabsf(pb.x - tb.x) + fabsf(pb.y - tb.y)
                       + fabsf(pb.z - tb.z) + fabsf(pb.w - tb.w);
        const float tx1 = tb.x - 0.5f * tb.z, ty1 = tb.y - 0.5f * tb.w;
        const float tx2 = tb.x + 0.5f * tb.z, ty2 = tb.y + 0.5f * tb.w;
        const float tarea = (tx2 - tx1) * (ty2 - ty1);
        const float iwr = fminf(px2, tx2) - fmaxf(px1, tx1);
        const float ihr = fminf(py2, ty2) - fmaxf(py1, ty1);
        const float inter = fmaxf(iwr, 0.0f) * fmaxf(ihr, 0.0f);
        const float uni = parea + tarea - inter;
        const float ew = (pb.z + tb.z) - iwr;
        const float eh = (pb.w + tb.w) - ihr;
        const float earea = ew * eh;
        const float num   = fmaf(uni, uni, earea * (inter - uni));
        const float gterm = __fdividef(num, uni * earea);
        float cost = fmaf(5.0f, l1, -cls);
        cost = fmaf(-2.0f, gterm, cost);
        __stcs(orow + t, cost);
    }
}

extern "C" void kernel_launch(void* const* d_in, const int* in_sizes, int n_in,
                              void* d_out, int out_size)
{
    const float* logits = (const float*)d_in[0];
    const float* boxes  = (const float*)d_in[1];
    const int*   labels = (const int*)  d_in[2];
    const float* tboxes = (const float*)d_in[3];
    float* out = (float*)d_out;

    const int BQ = in_sizes[1] / 4;          // pred_boxes is [BQ, 4]
    const int C  = in_sizes[0] / BQ;         // logits [BQ, C]
    const int T  = in_sizes[2];              // labels [T]

    if (C <= CPAD && (T % (BLOCK * TB)) == 0) {
        dim3 grid(1, (BQ + RB - 1) / RB);
        if (T == 2048)
            matcher_rt4_kernel<2048><<<grid, BLOCK>>>(logits, boxes, labels, tboxes, out, BQ, C, T);
        else
            matcher_rt4_kernel<0><<<grid, BLOCK>>>(logits, boxes, labels, tboxes, out, BQ, C, T);
    } else {
        matcher_fallback_kernel<<<BQ, BLOCK>>>(logits, boxes, labels, tboxes, out, C, T);
    }
}